// round 3
// baseline (speedup 1.0000x reference)
#include <cuda_runtime.h>

// ---------------------------------------------------------------------------
// BiSpikeNet forward, single persistent kernel. T=8, B=16, F=C*H*W=262144.
//
// 128 blocks (16 batches x 8 blocks/batch), 1024 threads. Membrane state in
// SMEM (128 KiB). x[t+1] is staged into a 96 KiB SMEM buffer via cp.async
// issued BEFORE the per-batch software barrier, so the copy completes in the
// barrier shadow (x loads do not depend on the normalization factor). The
// remaining 2/8 groups are L2-prefetched pre-barrier. Barrier release is a
// single broadcast float (1/denom) written by the last arriver. Spike bits
// live in registers; spike counts are popc'd once at the end.
// Global traffic: read x (128 MiB) + write out (16 MiB) only.
// ---------------------------------------------------------------------------

namespace {
constexpr int T_STEPS        = 8;
constexpr int BATCH          = 16;
constexpr int FDIM           = 1 << 18;          // 262144
constexpr int BLKS_PER_BATCH = 8;
constexpr int NBLOCKS        = BATCH * BLKS_PER_BATCH;   // 128
constexpr int NTHREADS       = 1024;
constexpr int EPB            = FDIM / BLKS_PER_BATCH;    // 32768 elems/block
constexpr int KG             = EPB / (NTHREADS * 4);     // 8 float4 groups/thread
constexpr int KSM            = 6;                        // groups staged in SMEM
constexpr int NHEADS         = 4;
constexpr int HID            = 64;
constexpr int NBAR           = (T_STEPS + 1) * BATCH;    // 144 counters
constexpr int SMEM_M_BYTES   = EPB * 4;                  // 128 KiB
constexpr int SMEM_X_BYTES   = KSM * NTHREADS * 16;      // 96 KiB
constexpr int SMEM_DYN       = SMEM_M_BYTES + SMEM_X_BYTES;
}

__device__ unsigned int g_bar[NBAR];
__device__ float g_invd[T_STEPS][BATCH];
__device__ float g_abs_part[T_STEPS][BATCH][BLKS_PER_BATCH];
__device__ unsigned int g_cnt_part[BATCH][BLKS_PER_BATCH][4];

__global__ void reset_kernel() {
    int i = threadIdx.x;
    if (i < NBAR) g_bar[i] = 0u;
    if (i < T_STEPS * BATCH) ((float*)g_invd)[i] = 0.0f;
}

__device__ __forceinline__ void l2_prefetch(const void* p) {
    asm volatile("prefetch.global.L2 [%0];" :: "l"(p));
}
__device__ __forceinline__ void cp_async16(unsigned int saddr, const void* gptr) {
    asm volatile("cp.async.cg.shared.global [%0], [%1], 16;"
                 :: "r"(saddr), "l"(gptr));
}
__device__ __forceinline__ void cp_commit() {
    asm volatile("cp.async.commit_group;");
}
__device__ __forceinline__ void cp_wait0() {
    asm volatile("cp.async.wait_group 0;" ::: "memory");
}

// one barrier + denom broadcast; returns 1/denom. Called by (warp0,lane0).
__device__ __forceinline__ float barrier_denom(int t, int b, int blk, float partial) {
    *(volatile float*)&g_abs_part[t][b][blk] = partial;
    __threadfence();
    unsigned old = atomicAdd(&g_bar[t * BATCH + b], 1u);
    if (old == BLKS_PER_BATCH - 1) {
        float tot = 0.0f;
        volatile float* pp = &g_abs_part[t][b][0];
#pragma unroll
        for (int i = 0; i < BLKS_PER_BATCH; i++) tot += pp[i];
        float dnm = tot * (1.0f / (float)FDIM) + 1e-6f;
        *(volatile float*)&g_invd[t][b] = 1.0f / dnm;
    }
    float iv;
    do { iv = *(volatile float*)&g_invd[t][b]; } while (iv == 0.0f);
    return iv;
}

__global__ void __launch_bounds__(NTHREADS, 1) bispike_kernel(
    const float* __restrict__ x,
    const float* __restrict__ decay_p,
    const float* __restrict__ vth_p,
    const float* __restrict__ W1,
    const float* __restrict__ b1,
    const float* __restrict__ W2,
    const float* __restrict__ b2,
    const float* __restrict__ att_w,
    float* __restrict__ out)
{
    extern __shared__ float smem_dyn[];
    float4* s_m4 = reinterpret_cast<float4*>(smem_dyn);                   // EPB floats
    float4* s_x4 = reinterpret_cast<float4*>((char*)smem_dyn + SMEM_M_BYTES);
    const unsigned int s_x_u32 =
        (unsigned int)__cvta_generic_to_shared((char*)smem_dyn + SMEM_M_BYTES);

    __shared__ float s_red[32];
    __shared__ unsigned int s_redc[32];
    __shared__ float s_h[NHEADS * HID];
    __shared__ float s_maps[32];
    __shared__ float s_aw[T_STEPS];
    __shared__ float s_invd;

    const int tid  = threadIdx.x;
    const int lane = tid & 31;
    const int warp = tid >> 5;
    const int b    = blockIdx.x >> 3;            // batch
    const int blk  = blockIdx.x & 7;             // slice within batch
    const int f0   = blk * EPB;

    const float d   = 1.0f / (1.0f + expf(-decay_p[0]));
    const float vth = vth_p[0];
    const float dvth = d * vth;

    unsigned int bits4[KG];                      // 4 elems x 8 step-bits per word
#pragma unroll
    for (int k = 0; k < KG; k++) bits4[k] = 0u;

    const float* xbase = x + (size_t)b * FDIM + f0;
    float inv_prev = 0.0f;

    // ================= t = 0: m = x, full LDG =================
    {
        const float4* xp = reinterpret_cast<const float4*>(xbase);
        float sa0 = 0.f, sa1 = 0.f, sa2 = 0.f, sa3 = 0.f;
#pragma unroll
        for (int k = 0; k < KG; k++) {
            const int idx4 = k * NTHREADS + tid;
            float4 xv = xp[idx4];
            s_m4[idx4] = xv;
            sa0 += fabsf(xv.x); sa1 += fabsf(xv.y);
            sa2 += fabsf(xv.z); sa3 += fabsf(xv.w);
        }
        // stage x[1] groups 0..5 into SMEM; prefetch groups 6,7 to L2
        const float* xn = xbase + (size_t)1 * BATCH * FDIM;
        const float4* xn4 = reinterpret_cast<const float4*>(xn);
#pragma unroll
        for (int k = 0; k < KSM; k++) {
            const int idx4 = k * NTHREADS + tid;
            cp_async16(s_x_u32 + idx4 * 16, &xn4[idx4]);
        }
        cp_commit();
        if ((lane & 7) == 0) {
            l2_prefetch(&xn4[6 * NTHREADS + tid]);
            l2_prefetch(&xn4[7 * NTHREADS + tid]);
        }

        float sum_abs = (sa0 + sa1) + (sa2 + sa3);
#pragma unroll
        for (int off = 16; off > 0; off >>= 1)
            sum_abs += __shfl_xor_sync(0xffffffffu, sum_abs, off);
        if (lane == 0) s_red[warp] = sum_abs;
        __syncthreads();
        if (warp == 0) {
            float v = s_red[lane];
#pragma unroll
            for (int off = 16; off > 0; off >>= 1)
                v += __shfl_xor_sync(0xffffffffu, v, off);
            if (lane == 0) s_invd = barrier_denom(0, b, blk, v);
        }
        __syncthreads();
        inv_prev = s_invd;
    }

    // ================= t = 1..7 =================
#pragma unroll
    for (int t = 1; t < T_STEPS; t++) {
        const float inv = inv_prev;
        const float4* xp = reinterpret_cast<const float4*>(
            xbase + (size_t)t * BATCH * FDIM);
        const float4* xn4 = reinterpret_cast<const float4*>(
            xbase + (size_t)(t + 1) * BATCH * FDIM);   // valid only if t<7

        // groups 6,7 via LDG first (L2-prefetched last step)
        float4 xr6 = xp[6 * NTHREADS + tid];
        float4 xr7 = xp[7 * NTHREADS + tid];

        cp_wait0();                                    // x[t] groups 0..5 ready

        float sa0 = 0.f, sa1 = 0.f, sa2 = 0.f, sa3 = 0.f;
#pragma unroll
        for (int k = 0; k < KSM; k++) {
            const int idx4 = k * NTHREADS + tid;
            float4 xv = s_x4[idx4];
            float4 mo = s_m4[idx4];
            float xa[4] = {xv.x, xv.y, xv.z, xv.w};
            float moa[4] = {mo.x, mo.y, mo.z, mo.w};
            float ma[4];
#pragma unroll
            for (int j = 0; j < 4; j++) {
                float mn = moa[j] * inv;
                bool  sp = (mn >= vth);
                if (sp) bits4[k] |= (1u << (8 * j + (t - 1)));
                ma[j] = fmaf(d, mn, xa[j]) - (sp ? dvth : 0.0f);
            }
            s_m4[idx4] = make_float4(ma[0], ma[1], ma[2], ma[3]);
            sa0 += fabsf(ma[0]); sa1 += fabsf(ma[1]);
            sa2 += fabsf(ma[2]); sa3 += fabsf(ma[3]);
            // refill this slot with x[t+1] (write lands >> after the LDS above)
            if (t < T_STEPS - 1)
                cp_async16(s_x_u32 + idx4 * 16, &xn4[idx4]);
        }
        if (t < T_STEPS - 1) {
            cp_commit();
            if ((lane & 7) == 0) {
                l2_prefetch(&xn4[6 * NTHREADS + tid]);
                l2_prefetch(&xn4[7 * NTHREADS + tid]);
            }
        }

        // groups 6,7
#pragma unroll
        for (int k = 6; k < 8; k++) {
            const int idx4 = k * NTHREADS + tid;
            float4 xv = (k == 6) ? xr6 : xr7;
            float4 mo = s_m4[idx4];
            float xa[4] = {xv.x, xv.y, xv.z, xv.w};
            float moa[4] = {mo.x, mo.y, mo.z, mo.w};
            float ma[4];
#pragma unroll
            for (int j = 0; j < 4; j++) {
                float mn = moa[j] * inv;
                bool  sp = (mn >= vth);
                if (sp) bits4[k] |= (1u << (8 * j + (t - 1)));
                ma[j] = fmaf(d, mn, xa[j]) - (sp ? dvth : 0.0f);
            }
            s_m4[idx4] = make_float4(ma[0], ma[1], ma[2], ma[3]);
            sa0 += fabsf(ma[0]); sa1 += fabsf(ma[1]);
            sa2 += fabsf(ma[2]); sa3 += fabsf(ma[3]);
        }

        float sum_abs = (sa0 + sa1) + (sa2 + sa3);
#pragma unroll
        for (int off = 16; off > 0; off >>= 1)
            sum_abs += __shfl_xor_sync(0xffffffffu, sum_abs, off);
        if (lane == 0) s_red[warp] = sum_abs;
        __syncthreads();
        if (warp == 0) {
            float v = s_red[lane];
#pragma unroll
            for (int off = 16; off > 0; off >>= 1)
                v += __shfl_xor_sync(0xffffffffu, v, off);
            if (lane == 0) s_invd = barrier_denom(t, b, blk, v);
        }
        __syncthreads();
        inv_prev = s_invd;
    }

    // ================= final spikes (t = T-1) =================
    {
        const float inv = inv_prev;
#pragma unroll
        for (int k = 0; k < KG; k++) {
            const int idx4 = k * NTHREADS + tid;
            float4 mo = s_m4[idx4];
            float moa[4] = {mo.x, mo.y, mo.z, mo.w};
#pragma unroll
            for (int j = 0; j < 4; j++)
                if (moa[j] * inv >= vth) bits4[k] |= (1u << (8 * j + 7));
        }
    }

    // ================= spike counts via popc, packed 2x16-bit ============
    {
        unsigned int packed[4];
#pragma unroll
        for (int p = 0; p < 4; p++) {
            unsigned int c_lo = 0, c_hi = 0;
            unsigned int m_lo = 0x01010101u << (2 * p);
            unsigned int m_hi = 0x01010101u << (2 * p + 1);
#pragma unroll
            for (int k = 0; k < KG; k++) {
                c_lo += __popc(bits4[k] & m_lo);
                c_hi += __popc(bits4[k] & m_hi);
            }
            packed[p] = c_lo | (c_hi << 16);
        }
#pragma unroll
        for (int p = 0; p < 4; p++) {
            unsigned int v = packed[p];
#pragma unroll
            for (int off = 16; off > 0; off >>= 1)
                v += __shfl_xor_sync(0xffffffffu, v, off);
            if (lane == 0) s_redc[warp] = v;
            __syncthreads();
            if (warp == 0) {
                unsigned int c = s_redc[lane];
#pragma unroll
                for (int off = 16; off > 0; off >>= 1)
                    c += __shfl_xor_sync(0xffffffffu, c, off);
                if (lane == 0)
                    *(volatile unsigned int*)&g_cnt_part[b][blk][p] = c;
            }
            __syncthreads();
        }
        if (warp == 0 && lane == 0) {
            __threadfence();
            unsigned int* bar = &g_bar[T_STEPS * BATCH + b];
            atomicAdd(bar, 1u);
            volatile unsigned int* ctr = bar;
            while (*ctr < (unsigned)BLKS_PER_BATCH) { }
        }
        __syncthreads();
    }

    // ================= tiny attention MLP (warp 0, per batch) ============
    if (warp == 0) {
        float summ[T_STEPS];
#pragma unroll
        for (int p = 0; p < 4; p++) {
            unsigned int lo = 0, hi = 0;
#pragma unroll
            for (int i = 0; i < BLKS_PER_BATCH; i++) {
                unsigned int v = *(volatile unsigned int*)&g_cnt_part[b][i][p];
                lo += v & 0xffffu;
                hi += v >> 16;
            }
            summ[2 * p]     = (float)lo * (1.0f / (float)FDIM);
            summ[2 * p + 1] = (float)hi * (1.0f / (float)FDIM);
        }
#pragma unroll
        for (int r = 0; r < 8; r++) {
            int idx = r * 32 + lane;
            float acc = b1[idx];
#pragma unroll
            for (int t = 0; t < T_STEPS; t++)
                acc += summ[t] * W1[idx * T_STEPS + t];
            s_h[idx] = fmaxf(acc, 0.0f);
        }
        __syncwarp();
        {
            float acc = b2[lane];
            const int hb = (lane >> 3) * HID;
            const float* w2p = W2 + lane * HID;
#pragma unroll
            for (int hd = 0; hd < HID; hd++)
                acc += s_h[hb + hd] * w2p[hd];
            s_maps[lane] = acc * att_w[lane >> 3];
        }
        __syncwarp();
        if (lane == 0) {
            float w[T_STEPS];
            float mx = -1e30f;
#pragma unroll
            for (int t = 0; t < T_STEPS; t++) {
                w[t] = s_maps[t] + s_maps[8 + t] + s_maps[16 + t] + s_maps[24 + t];
                mx = fmaxf(mx, w[t]);
            }
            float ssum = 0.0f;
#pragma unroll
            for (int t = 0; t < T_STEPS; t++) { w[t] = expf(w[t] - mx); ssum += w[t]; }
            float invs = 1.0f / ssum;
#pragma unroll
            for (int t = 0; t < T_STEPS; t++) s_aw[t] = w[t] * invs;
        }
    }
    __syncthreads();

    float aw[T_STEPS];
#pragma unroll
    for (int t = 0; t < T_STEPS; t++) aw[t] = s_aw[t];

    // ================= output: out[b,f] = sum_t aw[t]*spike(t,f) =========
    float4* op = reinterpret_cast<float4*>(out + (size_t)b * FDIM + f0);
#pragma unroll
    for (int k = 0; k < KG; k++) {
        unsigned int bt = bits4[k];
        float o[4];
#pragma unroll
        for (int j = 0; j < 4; j++) {
            float v = 0.0f;
#pragma unroll
            for (int t = 0; t < T_STEPS; t++)
                v += ((bt >> (8 * j + t)) & 1u) ? aw[t] : 0.0f;
            o[j] = v;
        }
        op[k * NTHREADS + tid] = make_float4(o[0], o[1], o[2], o[3]);
    }
}

extern "C" void kernel_launch(void* const* d_in, const int* in_sizes, int n_in,
                              void* d_out, int out_size) {
    (void)in_sizes; (void)n_in; (void)out_size;
    cudaFuncSetAttribute(bispike_kernel,
                         cudaFuncAttributeMaxDynamicSharedMemorySize, SMEM_DYN);
    reset_kernel<<<1, 256>>>();
    bispike_kernel<<<NBLOCKS, NTHREADS, SMEM_DYN>>>(
        (const float*)d_in[0],   // x
        (const float*)d_in[1],   // decay_param
        (const float*)d_in[2],   // v_th
        (const float*)d_in[3],   // W1
        (const float*)d_in[4],   // b1
        (const float*)d_in[5],   // W2
        (const float*)d_in[6],   // b2
        (const float*)d_in[7],   // att_w
        (float*)d_out);
}